// round 1
// baseline (speedup 1.0000x reference)
#include <cuda_runtime.h>
#include <cstdint>

#define TT  512
#define BBT 64
#define ICC 512
#define HCC 512
#define LLN 2

#define SCAN_BLOCKS 128   // 4 hidden dims per block, all co-resident on 148/152 SMs
#define DPB 4

// ---------------- scratch (device globals: no allocations allowed) ----------
__device__ float g_A1[TT * BBT * 2 * HCC];   // [T][B][1024]  x@W1x^T + b1  (r: 0..511, z: 512..1023)
__device__ float g_A2[TT * BBT * HCC];       // [T][B][512]   x@W2x^T + b2
__device__ float g_l0[TT * BBT * HCC];       // layer-0 output stream
__device__ float g_h [BBT * HCC];            // current hidden state [B][HC]
__device__ float g_rh[BBT * HCC];            // r*h                  [B][HC]
__device__ unsigned long long g_barGen;      // monotonic generation (survives graph replay)
__device__ unsigned int      g_barCnt;

// ---------------- grid barrier (sense-free, generation based) ---------------
__device__ __forceinline__ void grid_bar(unsigned long long target) {
    __syncthreads();
    if (threadIdx.x == 0) {
        __threadfence();
        unsigned prev = atomicAdd(&g_barCnt, 1u);
        if (prev == gridDim.x - 1u) {
            g_barCnt = 0u;
            __threadfence();
            atomicAdd(&g_barGen, 1ull);
        } else {
            while (((volatile unsigned long long*)&g_barGen)[0] < target) {
                __nanosleep(20);
            }
        }
        __threadfence();
    }
    __syncthreads();
}

// ---------------- precompute GEMM: A1/A2 = X @ Wx^T + b ---------------------
// C[M=32768][N=1536]; N<1024 -> g_A1 (W1 rows), N>=1024 -> g_A2 (W2 rows).
// BM=128, BN=64, BK=16, 256 threads, 8x4 micro-tile.
__global__ void __launch_bounds__(256) gru_pre(
    const float* __restrict__ Xext,
    const float* __restrict__ W1, const float* __restrict__ b1,
    const float* __restrict__ W2, const float* __restrict__ b2,
    int layer)
{
    const float* X   = (layer == 0) ? Xext : g_l0;
    const float* W1l = W1 + (size_t)layer * (2 * HCC) * (ICC + HCC);
    const float* W2l = W2 + (size_t)layer * HCC * (ICC + HCC);
    const float* b1l = b1 + layer * 2 * HCC;
    const float* b2l = b2 + layer * HCC;

    __shared__ float As[16][128];
    __shared__ float Bs[16][64];

    const int m0 = blockIdx.x * 128;
    const int n0 = blockIdx.y * 64;
    const int tid = threadIdx.x;
    const int isA1 = (n0 < 1024);
    const float* Wp = isA1 ? (W1l + (size_t)n0 * (ICC + HCC))
                           : (W2l + (size_t)(n0 - 1024) * (ICC + HCC));
    const int ty = tid >> 4;   // 0..15 -> 8 rows each
    const int tx = tid & 15;   // 0..15 -> 4 cols each

    float acc[8][4];
#pragma unroll
    for (int i = 0; i < 8; ++i)
#pragma unroll
        for (int j = 0; j < 4; ++j) acc[i][j] = 0.f;

    for (int k0 = 0; k0 < ICC; k0 += 16) {
#pragma unroll
        for (int r = 0; r < 2; ++r) {
            int q = tid + r * 256;           // 0..511 -> 128 rows x 4 float4
            int row = q >> 2, kf = (q & 3) * 4;
            float4 v = *reinterpret_cast<const float4*>(&X[(size_t)(m0 + row) * ICC + k0 + kf]);
            As[kf + 0][row] = v.x; As[kf + 1][row] = v.y;
            As[kf + 2][row] = v.z; As[kf + 3][row] = v.w;
        }
        {
            int row = tid >> 2, kf = (tid & 3) * 4;   // 64 rows x 4 float4
            float4 v = *reinterpret_cast<const float4*>(&Wp[(size_t)row * (ICC + HCC) + k0 + kf]);
            Bs[kf + 0][row] = v.x; Bs[kf + 1][row] = v.y;
            Bs[kf + 2][row] = v.z; Bs[kf + 3][row] = v.w;
        }
        __syncthreads();
#pragma unroll
        for (int k = 0; k < 16; ++k) {
            float4 a0 = *reinterpret_cast<const float4*>(&As[k][ty * 8]);
            float4 a1 = *reinterpret_cast<const float4*>(&As[k][ty * 8 + 4]);
            float4 bv = *reinterpret_cast<const float4*>(&Bs[k][tx * 4]);
            float av[8] = {a0.x, a0.y, a0.z, a0.w, a1.x, a1.y, a1.z, a1.w};
            float bw[4] = {bv.x, bv.y, bv.z, bv.w};
#pragma unroll
            for (int i = 0; i < 8; ++i)
#pragma unroll
                for (int j = 0; j < 4; ++j)
                    acc[i][j] = fmaf(av[i], bw[j], acc[i][j]);
        }
        __syncthreads();
    }

#pragma unroll
    for (int i = 0; i < 8; ++i)
#pragma unroll
        for (int j = 0; j < 4; ++j) {
            int m = m0 + ty * 8 + i;
            int n = n0 + tx * 4 + j;
            if (isA1) g_A1[(size_t)m * 1024 + n]         = acc[i][j] + b1l[n];
            else      g_A2[(size_t)m * 512 + (n - 1024)] = acc[i][j] + b2l[n - 1024];
        }
}

// ---------------- persistent scan kernel ------------------------------------
// 128 blocks x 256 threads. Block owns hidden dims j0..j0+3.
// Warp w handles batches 8w..8w+7 (two passes of 4); lanes split K (k = ln + 32m).
__global__ void __launch_bounds__(256, 1) gru_scan(
    const float* __restrict__ W1, const float* __restrict__ W2,
    const float* __restrict__ hiddens,
    float* __restrict__ dout, int layer)
{
    const int bid = blockIdx.x, tid = threadIdx.x;
    const int w = tid >> 5, ln = tid & 31;
    const int j0 = bid * DPB;

    __shared__ float sW1t[512][8];   // [k][o] : o<4 -> W1 row j0+o (r), o>=4 -> row 512+j0+o-4 (z)
    __shared__ float sW2t[512][4];   // [k][j]
    __shared__ float sZ[DPB][64];    // z[jd][b]
    __shared__ unsigned long long sBase;

    const float* W1l = W1 + (size_t)layer * (2 * HCC) * (ICC + HCC);
    const float* W2l = W2 + (size_t)layer * HCC * (ICC + HCC);
    float* outStream = (layer == 0) ? g_l0 : dout;
    float* hFinal = dout + (size_t)TT * BBT * HCC + (size_t)layer * BBT * HCC;

    if (tid == 0) sBase = ((volatile unsigned long long*)&g_barGen)[0];

    // resident weights (hidden halves, transposed)
    for (int idx = tid; idx < 512 * 8; idx += 256) {
        int k = idx >> 3, o = idx & 7;
        int row = (o < 4) ? (j0 + o) : (HCC + j0 + (o - 4));
        sW1t[k][o] = W1l[(size_t)row * (ICC + HCC) + ICC + k];
    }
    for (int idx = tid; idx < 512 * 4; idx += 256) {
        int k = idx >> 2, o = idx & 3;
        sW2t[k][o] = W2l[(size_t)(j0 + o) * (ICC + HCC) + ICC + k];
    }
    // init h for owned dims (broadcast h0 over batch)
    {
        int b = tid & 63, jd = tid >> 6;   // jd 0..3
        g_h[b * HCC + j0 + jd] = hiddens[layer * HCC + j0 + jd];
    }
    __syncthreads();

    unsigned long long bc = 0;
    grid_bar(sBase + (++bc));

    for (int t = 0; t < TT; ++t) {
        const float* A1t = g_A1 + (size_t)t * BBT * 1024;
        const float* A2t = g_A2 + (size_t)t * BBT * 512;

        // ---- stage 1: pre = A1 + h @ W1h^T ; r -> g_rh, z -> sZ -----------
#pragma unroll 1
        for (int pass = 0; pass < 2; ++pass) {
            const int bbase = 8 * w + pass * 4;
            float hreg[4][16];
#pragma unroll
            for (int b2 = 0; b2 < 4; ++b2)
#pragma unroll
                for (int m = 0; m < 16; ++m)
                    hreg[b2][m] = g_h[(bbase + b2) * HCC + ln + 32 * m];

            float acc[8][4];
#pragma unroll
            for (int o = 0; o < 8; ++o)
#pragma unroll
                for (int b2 = 0; b2 < 4; ++b2) acc[o][b2] = 0.f;

#pragma unroll
            for (int m = 0; m < 16; ++m) {
                float4 wlo = *reinterpret_cast<const float4*>(&sW1t[ln + 32 * m][0]);
                float4 whi = *reinterpret_cast<const float4*>(&sW1t[ln + 32 * m][4]);
#pragma unroll
                for (int b2 = 0; b2 < 4; ++b2) {
                    float hv = hreg[b2][m];
                    acc[0][b2] = fmaf(hv, wlo.x, acc[0][b2]);
                    acc[1][b2] = fmaf(hv, wlo.y, acc[1][b2]);
                    acc[2][b2] = fmaf(hv, wlo.z, acc[2][b2]);
                    acc[3][b2] = fmaf(hv, wlo.w, acc[3][b2]);
                    acc[4][b2] = fmaf(hv, whi.x, acc[4][b2]);
                    acc[5][b2] = fmaf(hv, whi.y, acc[5][b2]);
                    acc[6][b2] = fmaf(hv, whi.z, acc[6][b2]);
                    acc[7][b2] = fmaf(hv, whi.w, acc[7][b2]);
                }
            }
            // cross-lane reduce: (o,b2) pair -> lane o*4+b2
            float red = 0.f;
#pragma unroll
            for (int o = 0; o < 8; ++o)
#pragma unroll
                for (int b2 = 0; b2 < 4; ++b2) {
                    float v = acc[o][b2];
                    v += __shfl_xor_sync(0xFFFFFFFFu, v, 16);
                    v += __shfl_xor_sync(0xFFFFFFFFu, v, 8);
                    v += __shfl_xor_sync(0xFFFFFFFFu, v, 4);
                    v += __shfl_xor_sync(0xFFFFFFFFu, v, 2);
                    v += __shfl_xor_sync(0xFFFFFFFFu, v, 1);
                    if (ln == o * 4 + b2) red = v;
                }
            {
                int o = ln >> 2, b2 = ln & 3;
                int b = bbase + b2;
                if (o < 4) {
                    int j = j0 + o;
                    float pre = red + A1t[b * 1024 + j];
                    float s = 1.0f / (1.0f + __expf(-pre));
                    g_rh[b * HCC + j] = s * g_h[b * HCC + j];
                } else {
                    int jd = o - 4, j = j0 + jd;
                    float pre = red + A1t[b * 1024 + 512 + j];
                    sZ[jd][b] = 1.0f / (1.0f + __expf(-pre));
                }
            }
        }
        grid_bar(sBase + (++bc));

        // ---- stage 2: g = tanh(A2 + rh @ W2h^T); h = z*h + (1-z)*g --------
#pragma unroll 1
        for (int pass = 0; pass < 2; ++pass) {
            const int bbase = 8 * w + pass * 4;
            float rreg[4][16];
#pragma unroll
            for (int b2 = 0; b2 < 4; ++b2)
#pragma unroll
                for (int m = 0; m < 16; ++m)
                    rreg[b2][m] = g_rh[(bbase + b2) * HCC + ln + 32 * m];

            float acc2[4][4];
#pragma unroll
            for (int o = 0; o < 4; ++o)
#pragma unroll
                for (int b2 = 0; b2 < 4; ++b2) acc2[o][b2] = 0.f;

#pragma unroll
            for (int m = 0; m < 16; ++m) {
                float4 wv = *reinterpret_cast<const float4*>(&sW2t[ln + 32 * m][0]);
#pragma unroll
                for (int b2 = 0; b2 < 4; ++b2) {
                    float hv = rreg[b2][m];
                    acc2[0][b2] = fmaf(hv, wv.x, acc2[0][b2]);
                    acc2[1][b2] = fmaf(hv, wv.y, acc2[1][b2]);
                    acc2[2][b2] = fmaf(hv, wv.z, acc2[2][b2]);
                    acc2[3][b2] = fmaf(hv, wv.w, acc2[3][b2]);
                }
            }
            float red = 0.f;
#pragma unroll
            for (int o = 0; o < 4; ++o)
#pragma unroll
                for (int b2 = 0; b2 < 4; ++b2) {
                    float v = acc2[o][b2];
                    v += __shfl_xor_sync(0xFFFFFFFFu, v, 16);
                    v += __shfl_xor_sync(0xFFFFFFFFu, v, 8);
                    v += __shfl_xor_sync(0xFFFFFFFFu, v, 4);
                    v += __shfl_xor_sync(0xFFFFFFFFu, v, 2);
                    v += __shfl_xor_sync(0xFFFFFFFFu, v, 1);
                    if (ln == o * 4 + b2) red = v;
                }
            if (ln < 16) {
                int o = ln >> 2, b2 = ln & 3;
                int b = bbase + b2, j = j0 + o;
                float pre2 = red + A2t[b * 512 + j];
                float gg = tanhf(pre2);
                float z = sZ[o][b];
                float hn = fmaf(z, g_h[b * HCC + j] - gg, gg);  // z*h + (1-z)*g
                g_h[b * HCC + j] = hn;
                outStream[((size_t)t * BBT + b) * HCC + j] = hn;
                if (t == TT - 1) hFinal[b * HCC + j] = hn;
            }
        }
        grid_bar(sBase + (++bc));
    }
}

// ---------------- launch -----------------------------------------------------
extern "C" void kernel_launch(void* const* d_in, const int* in_sizes, int n_in,
                              void* d_out, int out_size)
{
    (void)in_sizes; (void)n_in; (void)out_size;
    const float* x       = (const float*)d_in[0];
    const float* hiddens = (const float*)d_in[1];
    const float* W1      = (const float*)d_in[2];
    const float* b1      = (const float*)d_in[3];
    const float* W2      = (const float*)d_in[4];
    const float* b2      = (const float*)d_in[5];
    float* out = (float*)d_out;

    dim3 pg(TT * BBT / 128, 1536 / 64);   // 256 x 24 blocks

    gru_pre <<<pg, 256>>>(x, W1, b1, W2, b2, 0);
    gru_scan<<<SCAN_BLOCKS, 256>>>(W1, W2, hiddens, out, 0);
    gru_pre <<<pg, 256>>>(x, W1, b1, W2, b2, 1);   // reads g_l0 internally
    gru_scan<<<SCAN_BLOCKS, 256>>>(W1, W2, hiddens, out, 1);
}

// round 2
// speedup vs baseline: 1.3508x; 1.3508x over previous
#include <cuda_runtime.h>
#include <cstdint>

#define TT  512
#define BBT 64
#define ICC 512
#define HCC 512
#define LLN 2

#define SCAN_BLOCKS 128
#define DPB 4

typedef unsigned long long ull;

// ---------------- scratch ----------------------------------------------------
__device__ float g_A1[TT * BBT * 2 * HCC];   // [T][B][1024]  (r: 0..511, z: 512..1023)
__device__ float g_A2[TT * BBT * HCC];       // [T][B][512]
__device__ float g_l0[TT * BBT * HCC];       // layer-0 output stream
__device__ float g_h [BBT * HCC];
__device__ float g_rh[BBT * HCC];
__device__ ull          g_barGen;
__device__ unsigned int g_barCnt;

// ---------------- f32x2 helpers ----------------------------------------------
__device__ __forceinline__ ull pk2(float a, float b) {
    ull r; asm("mov.b64 %0, {%1, %2};" : "=l"(r) : "f"(a), "f"(b)); return r;
}
__device__ __forceinline__ void upk2(ull v, float& a, float& b) {
    asm("mov.b64 {%0, %1}, %2;" : "=f"(a), "=f"(b) : "l"(v));
}
__device__ __forceinline__ void ffma2(ull& d, ull a, ull b) {
    asm("fma.rn.f32x2 %0, %1, %2, %0;" : "+l"(d) : "l"(a), "l"(b));
}

// ---------------- grid barrier ------------------------------------------------
__device__ __forceinline__ void grid_bar(ull target) {
    __syncthreads();
    if (threadIdx.x == 0) {
        __threadfence();
        unsigned prev = atomicAdd(&g_barCnt, 1u);
        if (prev == gridDim.x - 1u) {
            g_barCnt = 0u;
            __threadfence();
            atomicAdd(&g_barGen, 1ull);
        } else {
            while (*(volatile ull*)&g_barGen < target) { }
        }
        __threadfence();
    }
    __syncthreads();
}

// ---------------- multi-value butterfly reduce --------------------------------
// vals[32] per-thread; returns full cross-lane sum of vals[ln] (one output/lane).
__device__ __forceinline__ float bfly32(float* vals, int ln) {
#pragma unroll
    for (int off = 1; off < 32; off <<= 1) {
        const int n = 32 / (2 * off);
#pragma unroll
        for (int i = 0; i < n; ++i) {
            bool up = (ln & off);
            float send = up ? vals[2 * i] : vals[2 * i + 1];
            float got  = __shfl_xor_sync(0xFFFFFFFFu, send, off);
            float keep = up ? vals[2 * i + 1] : vals[2 * i];
            vals[i] = keep + got;
        }
    }
    return vals[0];
}

// ---------------- precompute GEMM: A1/A2 = X @ Wx^T + b -----------------------
// BM=128, BN=128, BK=16, 256 threads, 8x8 micro-tile with f32x2.
__global__ void __launch_bounds__(256) gru_pre(
    const float* __restrict__ Xext,
    const float* __restrict__ W1, const float* __restrict__ b1,
    const float* __restrict__ W2, const float* __restrict__ b2,
    int layer)
{
    const float* X   = (layer == 0) ? Xext : g_l0;
    const float* W1l = W1 + (size_t)layer * (2 * HCC) * (ICC + HCC);
    const float* W2l = W2 + (size_t)layer * HCC * (ICC + HCC);
    const float* b1l = b1 + layer * 2 * HCC;
    const float* b2l = b2 + layer * HCC;

    __shared__ float As[16][128];
    __shared__ float Bs[16][128];

    const int m0 = blockIdx.x * 128;
    const int n0 = blockIdx.y * 128;
    const int tid = threadIdx.x;
    const int isA1 = (n0 < 1024);
    const float* Wp = isA1 ? (W1l + (size_t)n0 * (ICC + HCC))
                           : (W2l + (size_t)(n0 - 1024) * (ICC + HCC));
    const int ty = tid >> 4;   // 0..15 -> 8 rows each
    const int tx = tid & 15;   // 0..15 -> 8 cols each

    ull acc[8][4];
#pragma unroll
    for (int i = 0; i < 8; ++i)
#pragma unroll
        for (int j = 0; j < 4; ++j) acc[i][j] = 0ull;

    for (int k0 = 0; k0 < ICC; k0 += 16) {
#pragma unroll
        for (int r = 0; r < 2; ++r) {
            int q = tid + r * 256;
            int row = q >> 2, kf = (q & 3) * 4;
            float4 v = *reinterpret_cast<const float4*>(&X[(size_t)(m0 + row) * ICC + k0 + kf]);
            As[kf + 0][row] = v.x; As[kf + 1][row] = v.y;
            As[kf + 2][row] = v.z; As[kf + 3][row] = v.w;
        }
#pragma unroll
        for (int r = 0; r < 2; ++r) {
            int q = tid + r * 256;
            int row = q >> 2, kf = (q & 3) * 4;
            float4 v = *reinterpret_cast<const float4*>(&Wp[(size_t)row * (ICC + HCC) + k0 + kf]);
            Bs[kf + 0][row] = v.x; Bs[kf + 1][row] = v.y;
            Bs[kf + 2][row] = v.z; Bs[kf + 3][row] = v.w;
        }
        __syncthreads();
#pragma unroll
        for (int k = 0; k < 16; ++k) {
            float4 a0 = *reinterpret_cast<const float4*>(&As[k][ty * 8]);
            float4 a1 = *reinterpret_cast<const float4*>(&As[k][ty * 8 + 4]);
            float4 b0 = *reinterpret_cast<const float4*>(&Bs[k][tx * 8]);
            float4 b1v = *reinterpret_cast<const float4*>(&Bs[k][tx * 8 + 4]);
            ull bp0 = pk2(b0.x, b0.y), bp1 = pk2(b0.z, b0.w);
            ull bp2 = pk2(b1v.x, b1v.y), bp3 = pk2(b1v.z, b1v.w);
            float av[8] = {a0.x, a0.y, a0.z, a0.w, a1.x, a1.y, a1.z, a1.w};
#pragma unroll
            for (int i = 0; i < 8; ++i) {
                ull ap = pk2(av[i], av[i]);
                ffma2(acc[i][0], ap, bp0);
                ffma2(acc[i][1], ap, bp1);
                ffma2(acc[i][2], ap, bp2);
                ffma2(acc[i][3], ap, bp3);
            }
        }
        __syncthreads();
    }

#pragma unroll
    for (int i = 0; i < 8; ++i) {
        int m = m0 + ty * 8 + i;
        int nb = n0 + tx * 8;
        float o[8];
#pragma unroll
        for (int j = 0; j < 4; ++j) upk2(acc[i][j], o[2 * j], o[2 * j + 1]);
        if (isA1) {
            float4 v0 = {o[0] + b1l[nb + 0], o[1] + b1l[nb + 1], o[2] + b1l[nb + 2], o[3] + b1l[nb + 3]};
            float4 v1 = {o[4] + b1l[nb + 4], o[5] + b1l[nb + 5], o[6] + b1l[nb + 6], o[7] + b1l[nb + 7]};
            *reinterpret_cast<float4*>(&g_A1[(size_t)m * 1024 + nb]) = v0;
            *reinterpret_cast<float4*>(&g_A1[(size_t)m * 1024 + nb + 4]) = v1;
        } else {
            int n2 = nb - 1024;
            float4 v0 = {o[0] + b2l[n2 + 0], o[1] + b2l[n2 + 1], o[2] + b2l[n2 + 2], o[3] + b2l[n2 + 3]};
            float4 v1 = {o[4] + b2l[n2 + 4], o[5] + b2l[n2 + 5], o[6] + b2l[n2 + 6], o[7] + b2l[n2 + 7]};
            *reinterpret_cast<float4*>(&g_A2[(size_t)m * 512 + n2]) = v0;
            *reinterpret_cast<float4*>(&g_A2[(size_t)m * 512 + n2 + 4]) = v1;
        }
    }
}

// ---------------- persistent scan kernel --------------------------------------
// 128 blocks x 512 threads. Block owns hidden dims j0..j0+3.
// Warp w handles batches 4w..4w+3; lanes split K (k = ln + 32m).
__global__ void __launch_bounds__(512, 1) gru_scan(
    const float* __restrict__ W1, const float* __restrict__ W2,
    const float* __restrict__ hiddens,
    float* __restrict__ dout, int layer)
{
    const int bid = blockIdx.x, tid = threadIdx.x;
    const int w = tid >> 5, ln = tid & 31;
    const int j0 = bid * DPB;
    const int bbase = w * 4;

    __shared__ float4 sW1a[512];   // [k] -> W1 r-rows j0..j0+3
    __shared__ float4 sW1b[512];   // [k] -> W1 z-rows 512+j0..+3
    __shared__ float4 sW2a[512];   // [k] -> W2 rows j0..j0+3
    __shared__ float  sZ[DPB][64];
    __shared__ float  sH[DPB][64];
    __shared__ ull    sBase;

    const float* W1l = W1 + (size_t)layer * (2 * HCC) * (ICC + HCC);
    const float* W2l = W2 + (size_t)layer * HCC * (ICC + HCC);
    float* outStream = (layer == 0) ? g_l0 : dout;
    float* hFinal = dout + (size_t)TT * BBT * HCC + (size_t)layer * BBT * HCC;

    if (tid == 0) sBase = *(volatile ull*)&g_barGen;

    // resident weights (hidden halves, transposed into float4-per-k)
    for (int k = tid; k < 512; k += 512) {
        float4 a, b, c;
        a.x = W1l[(size_t)(j0 + 0) * 1024 + 512 + k];
        a.y = W1l[(size_t)(j0 + 1) * 1024 + 512 + k];
        a.z = W1l[(size_t)(j0 + 2) * 1024 + 512 + k];
        a.w = W1l[(size_t)(j0 + 3) * 1024 + 512 + k];
        b.x = W1l[(size_t)(512 + j0 + 0) * 1024 + 512 + k];
        b.y = W1l[(size_t)(512 + j0 + 1) * 1024 + 512 + k];
        b.z = W1l[(size_t)(512 + j0 + 2) * 1024 + 512 + k];
        b.w = W1l[(size_t)(512 + j0 + 3) * 1024 + 512 + k];
        c.x = W2l[(size_t)(j0 + 0) * 1024 + 512 + k];
        c.y = W2l[(size_t)(j0 + 1) * 1024 + 512 + k];
        c.z = W2l[(size_t)(j0 + 2) * 1024 + 512 + k];
        c.w = W2l[(size_t)(j0 + 3) * 1024 + 512 + k];
        sW1a[k] = a; sW1b[k] = b; sW2a[k] = c;
    }
    if (tid < 256) {
        int b = tid & 63, jd = tid >> 6;
        float v = hiddens[layer * HCC + j0 + jd];
        g_h[b * HCC + j0 + jd] = v;
        sH[jd][b] = v;
    }
    __syncthreads();

    ull bc = 0;
    grid_bar(sBase + (++bc));

    for (int t = 0; t < TT; ++t) {
        const float* A1t = g_A1 + (size_t)t * BBT * 1024;
        const float* A2t = g_A2 + (size_t)t * BBT * 512;

        // ---- stage 1: pre = A1 + h @ W1h^T ; r -> g_rh, z -> sZ --------------
        {
            ull acc[4][4];   // [opair][b2]
#pragma unroll
            for (int i = 0; i < 4; ++i)
#pragma unroll
                for (int j = 0; j < 4; ++j) acc[i][j] = 0ull;

#pragma unroll 1
            for (int half = 0; half < 2; ++half) {
                float hs[4][8];
#pragma unroll
                for (int mm = 0; mm < 8; ++mm)
#pragma unroll
                    for (int b2 = 0; b2 < 4; ++b2)
                        hs[b2][mm] = __ldcg(&g_h[(bbase + b2) * HCC + ln + 32 * (half * 8 + mm)]);
#pragma unroll
                for (int mm = 0; mm < 8; ++mm) {
                    int k = ln + 32 * (half * 8 + mm);
                    float4 wl = sW1a[k];
                    float4 wh = sW1b[k];
                    ull w0 = pk2(wl.x, wl.y), w1 = pk2(wl.z, wl.w);
                    ull w2 = pk2(wh.x, wh.y), w3 = pk2(wh.z, wh.w);
#pragma unroll
                    for (int b2 = 0; b2 < 4; ++b2) {
                        ull hp = pk2(hs[b2][mm], hs[b2][mm]);
                        ffma2(acc[0][b2], w0, hp);
                        ffma2(acc[1][b2], w1, hp);
                        ffma2(acc[2][b2], w2, hp);
                        ffma2(acc[3][b2], w3, hp);
                    }
                }
            }
            float vals[32];
#pragma unroll
            for (int i = 0; i < 4; ++i)
#pragma unroll
                for (int b2 = 0; b2 < 4; ++b2) {
                    float x, y;
                    upk2(acc[i][b2], x, y);
                    vals[(2 * i + 0) * 4 + b2] = x;
                    vals[(2 * i + 1) * 4 + b2] = y;
                }
            float red = bfly32(vals, ln);

            int o = ln >> 2, b2 = ln & 3;
            int b = bbase + b2;
            if (o < 4) {
                int j = j0 + o;
                float pre = red + A1t[b * 1024 + j];
                float s = 1.0f / (1.0f + __expf(-pre));
                g_rh[b * HCC + j] = s * sH[o][b];
            } else {
                int jd = o - 4;
                float pre = red + A1t[b * 1024 + 512 + j0 + jd];
                sZ[jd][b] = 1.0f / (1.0f + __expf(-pre));
            }
        }
        grid_bar(sBase + (++bc));

        // ---- stage 2: g = tanh(A2 + rh @ W2h^T); h = z*h + (1-z)*g -----------
        {
            ull acc2[2][4];
#pragma unroll
            for (int i = 0; i < 2; ++i)
#pragma unroll
                for (int j = 0; j < 4; ++j) acc2[i][j] = 0ull;

#pragma unroll 1
            for (int half = 0; half < 2; ++half) {
                float rs[4][8];
#pragma unroll
                for (int mm = 0; mm < 8; ++mm)
#pragma unroll
                    for (int b2 = 0; b2 < 4; ++b2)
                        rs[b2][mm] = __ldcg(&g_rh[(bbase + b2) * HCC + ln + 32 * (half * 8 + mm)]);
#pragma unroll
                for (int mm = 0; mm < 8; ++mm) {
                    int k = ln + 32 * (half * 8 + mm);
                    float4 wv = sW2a[k];
                    ull w0 = pk2(wv.x, wv.y), w1 = pk2(wv.z, wv.w);
#pragma unroll
                    for (int b2 = 0; b2 < 4; ++b2) {
                        ull hp = pk2(rs[b2][mm], rs[b2][mm]);
                        ffma2(acc2[0][b2], w0, hp);
                        ffma2(acc2[1][b2], w1, hp);
                    }
                }
            }
            float vals[32];
#pragma unroll
            for (int i = 0; i < 2; ++i)
#pragma unroll
                for (int b2 = 0; b2 < 4; ++b2) {
                    float x, y;
                    upk2(acc2[i][b2], x, y);
                    vals[(2 * i + 0) * 4 + b2] = x;
                    vals[(2 * i + 1) * 4 + b2] = y;
                }
#pragma unroll
            for (int i = 16; i < 32; ++i) vals[i] = 0.f;
            float red = bfly32(vals, ln);

            if (ln < 16) {
                int o = ln >> 2, b2 = ln & 3;
                int b = bbase + b2, j = j0 + o;
                float pre2 = red + A2t[b * 512 + j];
                float gg = tanhf(pre2);
                float z = sZ[o][b];
                float hold = sH[o][b];
                float hn = fmaf(z, hold - gg, gg);
                sH[o][b] = hn;
                g_h[b * HCC + j] = hn;
                outStream[((size_t)t * BBT + b) * HCC + j] = hn;
                if (t == TT - 1) hFinal[b * HCC + j] = hn;
            }
        }
        grid_bar(sBase + (++bc));
    }
}

// ---------------- launch -------------------------------------------------------
extern "C" void kernel_launch(void* const* d_in, const int* in_sizes, int n_in,
                              void* d_out, int out_size)
{
    (void)in_sizes; (void)n_in; (void)out_size;
    const float* x       = (const float*)d_in[0];
    const float* hiddens = (const float*)d_in[1];
    const float* W1      = (const float*)d_in[2];
    const float* b1      = (const float*)d_in[3];
    const float* W2      = (const float*)d_in[4];
    const float* b2      = (const float*)d_in[5];
    float* out = (float*)d_out;

    dim3 pg(TT * BBT / 128, 1536 / 128);   // 256 x 12 blocks

    gru_pre <<<pg, 256>>>(x, W1, b1, W2, b2, 0);
    gru_scan<<<SCAN_BLOCKS, 512>>>(W1, W2, hiddens, out, 0);
    gru_pre <<<pg, 256>>>(x, W1, b1, W2, b2, 1);
    gru_scan<<<SCAN_BLOCKS, 512>>>(W1, W2, hiddens, out, 1);
}